// round 1
// baseline (speedup 1.0000x reference)
#include <cuda_runtime.h>
#include <cuda_bf16.h>
#include <cstdint>

// Problem shape (fixed for this bench)
#define Bdim 128
#define Tdim 784
#define Idim 512   // K of branch GEMMs
#define Hdim 512   // N of branch GEMMs
#define Odim 10
#define Mdim (Bdim * Tdim)   // 100352

// ---------------------------------------------------------------------------
// Scratch (device globals: allocation inside kernel_launch is forbidden)
// ---------------------------------------------------------------------------
__device__ float g_d1[(size_t)Mdim * Hdim];     // [B*T, H] branch-1 projections
__device__ float g_d2[(size_t)Mdim * Hdim];     // [B*T, H] branch-2 projections
__device__ float g_spk[(size_t)Mdim * Hdim];    // [B*T, H] spikes (0/1 as float)

// ---------------------------------------------------------------------------
// Kernel A: dual branch SGEMM  D = X @ W^T + b
//   X: [M, K] row-major, W: [N, K] row-major (both K-contiguous -> NT gemm)
//   blockIdx.z in {0,1} selects (W1,b1,g_d1) vs (W2,b2,g_d2)
//   BM=128, BN=128, BK=16, 256 threads, 8x8 per-thread tile
// ---------------------------------------------------------------------------
#define BM 128
#define BN 128
#define BK 16
#define XS_LD (BM + 4)
#define WS_LD (BN + 4)

__global__ void __launch_bounds__(256, 2) dual_gemm_kernel(
    const float* __restrict__ X,
    const float* __restrict__ W1, const float* __restrict__ b1,
    const float* __restrict__ W2, const float* __restrict__ b2)
{
    __shared__ float Xs[BK * XS_LD];
    __shared__ float Ws[BK * WS_LD];

    const float* W    = blockIdx.z ? W2 : W1;
    const float* bias = blockIdx.z ? b2 : b1;
    float*       D    = blockIdx.z ? g_d2 : g_d1;

    const int m0 = blockIdx.y * BM;
    const int n0 = blockIdx.x * BN;

    const int tid  = threadIdx.x;          // 0..255
    const int lrow = tid >> 2;             // 0..63
    const int lcol = (tid & 3) * 4;        // 0,4,8,12

    const int tx = tid & 15;               // 0..15 (N direction)
    const int ty = tid >> 4;               // 0..15 (M direction)

    float acc[8][8];
    #pragma unroll
    for (int i = 0; i < 8; i++)
        #pragma unroll
        for (int j = 0; j < 8; j++) acc[i][j] = 0.f;

    for (int k0 = 0; k0 < Idim; k0 += BK) {
        // Load X tile [BM x BK] -> Xs[k][m]  (transposed store)
        #pragma unroll
        for (int r = 0; r < 2; r++) {
            int row = lrow + r * 64;
            float4 v = *(const float4*)&X[(size_t)(m0 + row) * Idim + k0 + lcol];
            Xs[(lcol + 0) * XS_LD + row] = v.x;
            Xs[(lcol + 1) * XS_LD + row] = v.y;
            Xs[(lcol + 2) * XS_LD + row] = v.z;
            Xs[(lcol + 3) * XS_LD + row] = v.w;
        }
        // Load W tile [BN x BK] -> Ws[k][n]
        #pragma unroll
        for (int r = 0; r < 2; r++) {
            int row = lrow + r * 64;
            float4 v = *(const float4*)&W[(size_t)(n0 + row) * Idim + k0 + lcol];
            Ws[(lcol + 0) * WS_LD + row] = v.x;
            Ws[(lcol + 1) * WS_LD + row] = v.y;
            Ws[(lcol + 2) * WS_LD + row] = v.z;
            Ws[(lcol + 3) * WS_LD + row] = v.w;
        }
        __syncthreads();

        #pragma unroll
        for (int kk = 0; kk < BK; kk++) {
            float4 a0 = *(const float4*)&Xs[kk * XS_LD + ty * 8];
            float4 a1 = *(const float4*)&Xs[kk * XS_LD + ty * 8 + 4];
            float4 c0 = *(const float4*)&Ws[kk * WS_LD + tx * 8];
            float4 c1 = *(const float4*)&Ws[kk * WS_LD + tx * 8 + 4];
            float a[8] = {a0.x, a0.y, a0.z, a0.w, a1.x, a1.y, a1.z, a1.w};
            float c[8] = {c0.x, c0.y, c0.z, c0.w, c1.x, c1.y, c1.z, c1.w};
            #pragma unroll
            for (int i = 0; i < 8; i++)
                #pragma unroll
                for (int j = 0; j < 8; j++)
                    acc[i][j] = fmaf(a[i], c[j], acc[i][j]);
        }
        __syncthreads();
    }

    // Epilogue: add bias, store
    #pragma unroll
    for (int i = 0; i < 8; i++) {
        int m = m0 + ty * 8 + i;
        #pragma unroll
        for (int j = 0; j < 8; j += 4) {
            int n = n0 + tx * 8 + j;
            float4 v;
            v.x = acc[i][j + 0] + bias[n + 0];
            v.y = acc[i][j + 1] + bias[n + 1];
            v.z = acc[i][j + 2] + bias[n + 2];
            v.w = acc[i][j + 3] + bias[n + 3];
            *(float4*)&D[(size_t)m * Hdim + n] = v;
        }
    }
}

// ---------------------------------------------------------------------------
// Kernel B: sequential LIF scan over T. One thread per (b,h).
// ---------------------------------------------------------------------------
__device__ __forceinline__ float sigmoidf(float x) {
    return 1.f / (1.f + expf(-x));
}

__global__ void __launch_bounds__(256) scan_kernel(
    const float* __restrict__ tau_m,
    const float* __restrict__ tau_n1,
    const float* __restrict__ tau_n2,
    const float* __restrict__ mem0,
    const float* __restrict__ spike0)
{
    const int tid = blockIdx.x * blockDim.x + threadIdx.x;   // 0..B*H-1
    const int b = tid / Hdim;
    const int h = tid - b * Hdim;

    const float alpha  = sigmoidf(tau_m[h]);
    const float beta1  = sigmoidf(tau_n1[h]);
    const float beta2  = sigmoidf(tau_n2[h]);
    const float om_a   = 1.f - alpha;
    const float om_b1  = 1.f - beta1;
    const float om_b2  = 1.f - beta2;

    float mem = mem0[tid];
    float spk = spike0[tid];
    float d1 = 0.f, d2 = 0.f;

    size_t base = ((size_t)b * Tdim) * Hdim + h;
    const float* __restrict__ D1 = g_d1;
    const float* __restrict__ D2 = g_d2;
    float* __restrict__ S = g_spk;

    #pragma unroll 4
    for (int t = 0; t < Tdim; t++) {
        float d1t = D1[base];
        float d2t = D2[base];
        d1 = beta1 * d1 + om_b1 * d1t;
        d2 = beta2 * d2 + om_b2 * d2t;
        float total = d1 + d2;
        mem = mem * alpha + om_a * total - spk;   // V_TH = 1
        spk = (mem > 1.f) ? 1.f : 0.f;            // spike_fn(mem - V_TH)
        S[base] = spk;
        base += Hdim;
    }
}

// ---------------------------------------------------------------------------
// Kernel C: readout  out[m, o] = sum_h S[m,h] * Wr[o,h] + br[o]
// One warp per row m. Wr staged in shared memory.
// ---------------------------------------------------------------------------
__global__ void __launch_bounds__(256) readout_kernel(
    const float* __restrict__ Wr,
    const float* __restrict__ br,
    float* __restrict__ Out)
{
    __shared__ float WrS[Odim * Hdim];   // 20 KB
    __shared__ float brS[Odim];
    for (int i = threadIdx.x; i < Odim * Hdim; i += blockDim.x) WrS[i] = Wr[i];
    if (threadIdx.x < Odim) brS[threadIdx.x] = br[threadIdx.x];
    __syncthreads();

    const int warp = threadIdx.x >> 5;
    const int lane = threadIdx.x & 31;
    const int m = blockIdx.x * 8 + warp;          // 8 warps per block
    const float* __restrict__ row = g_spk + (size_t)m * Hdim;

    float acc[Odim];
    #pragma unroll
    for (int o = 0; o < Odim; o++) acc[o] = 0.f;

    #pragma unroll
    for (int hh = lane; hh < Hdim; hh += 32) {
        float s = row[hh];
        #pragma unroll
        for (int o = 0; o < Odim; o++)
            acc[o] = fmaf(s, WrS[o * Hdim + hh], acc[o]);
    }

    #pragma unroll
    for (int o = 0; o < Odim; o++)
        #pragma unroll
        for (int d = 16; d; d >>= 1)
            acc[o] += __shfl_xor_sync(0xffffffffu, acc[o], d);

    if (lane == 0) {
        #pragma unroll
        for (int o = 0; o < Odim; o++)
            Out[(size_t)m * Odim + o] = acc[o] + brS[o];
    }
}

// ---------------------------------------------------------------------------
// Launch
// ---------------------------------------------------------------------------
extern "C" void kernel_launch(void* const* d_in, const int* in_sizes, int n_in,
                              void* d_out, int out_size)
{
    const float* input_data = (const float*)d_in[0];   // [B,T,I]
    const float* W1     = (const float*)d_in[1];       // [H,I]
    const float* b1     = (const float*)d_in[2];       // [H]
    const float* W2     = (const float*)d_in[3];       // [H,I]
    const float* b2     = (const float*)d_in[4];       // [H]
    const float* tau_m  = (const float*)d_in[5];       // [H]
    const float* tau_n1 = (const float*)d_in[6];       // [H]
    const float* tau_n2 = (const float*)d_in[7];       // [H]
    const float* Wr     = (const float*)d_in[8];       // [O,H]
    const float* br     = (const float*)d_in[9];       // [O]
    const float* mem0   = (const float*)d_in[10];      // [B,H]
    const float* spike0 = (const float*)d_in[11];      // [B,H]
    float* out = (float*)d_out;                        // [B,T,O]

    (void)in_sizes; (void)n_in; (void)out_size;

    // A: branch projections (both branches via grid.z)
    dim3 ggrid(Hdim / BN, Mdim / BM, 2);               // (4, 784, 2)
    dual_gemm_kernel<<<ggrid, 256>>>(input_data, W1, b1, W2, b2);

    // B: sequential scan, one thread per (b,h)
    scan_kernel<<<(Bdim * Hdim) / 256, 256>>>(tau_m, tau_n1, tau_n2, mem0, spike0);

    // C: readout
    readout_kernel<<<Mdim / 8, 256>>>(Wr, br, out);
}